// round 11
// baseline (speedup 1.0000x reference)
#include <cuda_runtime.h>
#include <cuda_bf16.h>
#include <math.h>
#include <cstdint>

#define N_ROWS 8192
#define K_DIM  512
#define F_DIM  256
#define NCHUNK 1024
#define CHUNK  8

// ---------------- scratch (device globals) ----------------
__device__ __nv_bfloat16 g_xh[N_ROWS * K_DIM];
__device__ __nv_bfloat16 g_xl[N_ROWS * K_DIM];
__device__ __nv_bfloat16 g_wth[F_DIM * K_DIM];   // W^T hi  [256][512]
__device__ __nv_bfloat16 g_wtl[F_DIM * K_DIM];   // W^T lo
__device__ float g_h[N_ROWS * F_DIM];
__device__ float g_f[N_ROWS];
__device__ float g_g[N_ROWS];
__device__ float g_gs[N_ROWS];
__device__ int   g_gidx[N_ROWS];
__device__ int   g_rank[N_ROWS];
__device__ int   g_cnt[N_ROWS];
// local scans: row k = [locH prefix (256) | locE suffix (256)]
__device__ float g_loc[(size_t)(N_ROWS + 1) * 512];
// chunk offsets: row b = [choffH (256) | choffE (256)]
__device__ float g_choff[(size_t)(NCHUNK + 1) * 512];
__device__ float g_aggH[NCHUNK * F_DIM];
__device__ float g_aggE[NCHUNK * F_DIM];
__device__ float g_aggW[NCHUNK];
__device__ float g_lsufW[N_ROWS + 1];
__device__ float g_choffW[NCHUNK + 1];

// ---------------- helpers ----------------
__device__ __forceinline__ uint32_t smem_u32(const void* p) {
    uint32_t a;
    asm("{ .reg .u64 t; cvta.to.shared.u64 t, %1; cvt.u32.u64 %0, t; }" : "=r"(a) : "l"(p));
    return a;
}
__device__ __forceinline__ void ldsm_x4(uint32_t (&r)[4], uint32_t addr) {
    asm volatile("ldmatrix.sync.aligned.m8n8.x4.shared.b16 {%0,%1,%2,%3}, [%4];"
                 : "=r"(r[0]), "=r"(r[1]), "=r"(r[2]), "=r"(r[3]) : "r"(addr));
}
__device__ __forceinline__ void mma16816(float (&d)[4], const uint32_t (&a)[4],
                                         uint32_t b0, uint32_t b1) {
    asm volatile(
        "mma.sync.aligned.m16n8k16.row.col.f32.bf16.bf16.f32 "
        "{%0,%1,%2,%3}, {%4,%5,%6,%7}, {%8,%9}, {%0,%1,%2,%3};"
        : "+f"(d[0]), "+f"(d[1]), "+f"(d[2]), "+f"(d[3])
        : "r"(a[0]), "r"(a[1]), "r"(a[2]), "r"(a[3]), "r"(b0), "r"(b1));
}
__device__ __forceinline__ void cp16(uint32_t dst, const void* src) {
    asm volatile("cp.async.cg.shared.global [%0], [%1], 16;" :: "r"(dst), "l"(src));
}

// ---------------- 0) fused convert: x (4 float4/thread) + W + zero-inits ------
#define XBLOCKS (N_ROWS * K_DIM / 4096)   // 1024 blocks, 16 floats per thread
#define WBLOCKS (K_DIM * F_DIM / 256)     // 512
__global__ void convert_kernel(const float* __restrict__ x, const float* __restrict__ W) {
    if (blockIdx.x < XBLOCKS) {
        const int base = blockIdx.x * 4096;
        float4 v[4];
        #pragma unroll
        for (int l = 0; l < 4; l++)
            v[l] = *(const float4*)(x + base + l * 1024 + threadIdx.x * 4);
        #pragma unroll
        for (int l = 0; l < 4; l++) {
            const int idx = base + l * 1024 + threadIdx.x * 4;
            __nv_bfloat16 h0 = __float2bfloat16_rn(v[l].x), h1 = __float2bfloat16_rn(v[l].y);
            __nv_bfloat16 h2 = __float2bfloat16_rn(v[l].z), h3 = __float2bfloat16_rn(v[l].w);
            __nv_bfloat16 l0 = __float2bfloat16_rn(v[l].x - __bfloat162float(h0));
            __nv_bfloat16 l1 = __float2bfloat16_rn(v[l].y - __bfloat162float(h1));
            __nv_bfloat16 l2 = __float2bfloat16_rn(v[l].z - __bfloat162float(h2));
            __nv_bfloat16 l3 = __float2bfloat16_rn(v[l].w - __bfloat162float(h3));
            __nv_bfloat162* ph = (__nv_bfloat162*)(g_xh + idx);
            __nv_bfloat162* pl = (__nv_bfloat162*)(g_xl + idx);
            ph[0] = __nv_bfloat162(h0, h1); ph[1] = __nv_bfloat162(h2, h3);
            pl[0] = __nv_bfloat162(l0, l1); pl[1] = __nv_bfloat162(l2, l3);
        }
    } else {
        const int idx = (blockIdx.x - XBLOCKS) * 256 + threadIdx.x;  // 0..131071
        if (idx < N_ROWS) {
            g_rank[idx] = 0; g_cnt[idx] = 0;
            g_f[idx] = 0.f;  g_g[idx] = 0.f;
        }
        const int k = idx >> 8;
        const int n = idx & 255;
        float v = W[idx];
        __nv_bfloat16 h = __float2bfloat16_rn(v);
        __nv_bfloat16 l = __float2bfloat16_rn(v - __bfloat162float(h));
        g_wth[(size_t)n * K_DIM + k] = h;
        g_wtl[(size_t)n * K_DIM + k] = l;
    }
}

// ---------------- 1) mma.sync GEMM: 128x128 tile, K-chunk 64 (R7 config) --------
#define GSTRIDE 72
#define TILE_B  18432
#define BUFSZ   73728
#define SM_A1A2 (2 * BUFSZ)

__device__ __forceinline__ void load_chunk_async(uint32_t sb, int buf, int k0,
                                                 int bm, int bn, int tid) {
    uint32_t base = sb + buf * BUFSZ;
    #pragma unroll
    for (int l = 0; l < 4; l++) {
        int idx = tid + l * 256;
        int r = idx >> 3, c8 = (idx & 7) * 8;
        uint32_t off = (uint32_t)(r * GSTRIDE + c8) * 2;
        cp16(base + off,              g_xh  + (size_t)(bm + r) * K_DIM + k0 + c8);
        cp16(base + TILE_B + off,     g_xl  + (size_t)(bm + r) * K_DIM + k0 + c8);
        cp16(base + 2 * TILE_B + off, g_wth + (size_t)(bn + r) * K_DIM + k0 + c8);
        cp16(base + 3 * TILE_B + off, g_wtl + (size_t)(bn + r) * K_DIM + k0 + c8);
    }
}

__global__ void __launch_bounds__(256, 1) gemm_mma_kernel(const float* __restrict__ a) {
    extern __shared__ char smem[];
    const uint32_t sb = smem_u32(smem);
    float* sa = (float*)(smem + SM_A1A2);
    const int tid = threadIdx.x;
    const int wid = tid >> 5, lane = tid & 31;
    const int warp_m = wid >> 2;
    const int warp_n = wid & 3;
    const int bm = blockIdx.y * 128;
    const int bn = blockIdx.x * 128;

    float acc[4][4][4];
    #pragma unroll
    for (int mt = 0; mt < 4; mt++)
        #pragma unroll
        for (int nt = 0; nt < 4; nt++)
            #pragma unroll
            for (int r = 0; r < 4; r++) acc[mt][nt][r] = 0.f;

    const int a_row = warp_m * 64 + (lane & 15);
    const int a_col = (lane >> 4) * 8;
    const int b_row = warp_n * 32 + ((lane >> 4) & 1) * 8 + (lane & 7);
    const int b_col = ((lane >> 3) & 1) * 8;

    sa[tid] = a[tid];
    sa[256 + tid] = a[256 + tid];
    load_chunk_async(sb, 0, 0, bm, bn, tid);
    asm volatile("cp.async.commit_group;" ::: "memory");

    for (int i = 0; i < 8; i++) {
        asm volatile("cp.async.wait_group 0;" ::: "memory");
        __syncthreads();
        if (i < 7) {
            load_chunk_async(sb, (i & 1) ^ 1, (i + 1) * 64, bm, bn, tid);
            asm volatile("cp.async.commit_group;" ::: "memory");
        }
        const uint32_t bufb = sb + (i & 1) * BUFSZ;
        #pragma unroll
        for (int kk = 0; kk < 4; kk++) {
            uint32_t ah[4][4], al[4][4], bh[2][4], bl[2][4];
            #pragma unroll
            for (int mt = 0; mt < 4; mt++) {
                uint32_t off = (uint32_t)((a_row + mt * 16) * GSTRIDE + kk * 16 + a_col) * 2;
                ldsm_x4(ah[mt], bufb + off);
                ldsm_x4(al[mt], bufb + TILE_B + off);
            }
            #pragma unroll
            for (int np = 0; np < 2; np++) {
                uint32_t off = (uint32_t)((b_row + np * 16) * GSTRIDE + kk * 16 + b_col) * 2;
                ldsm_x4(bh[np], bufb + 2 * TILE_B + off);
                ldsm_x4(bl[np], bufb + 3 * TILE_B + off);
            }
            #pragma unroll
            for (int mt = 0; mt < 4; mt++) {
                #pragma unroll
                for (int nt = 0; nt < 4; nt++) {
                    int np = nt >> 1, p = (nt & 1) * 2;
                    mma16816(acc[mt][nt], ah[mt], bh[np][p], bh[np][p + 1]);
                    mma16816(acc[mt][nt], ah[mt], bl[np][p], bl[np][p + 1]);
                    mma16816(acc[mt][nt], al[mt], bh[np][p], bh[np][p + 1]);
                }
            }
        }
        __syncthreads();
    }

    // epilogue: write h + fused f/g partial dot products
    const int g = lane >> 2, t = lane & 3;
    #pragma unroll
    for (int mt = 0; mt < 4; mt++) {
        const int row = bm + warp_m * 64 + mt * 16 + g;
        float f0 = 0.f, g0 = 0.f, f1 = 0.f, g1 = 0.f;
        #pragma unroll
        for (int nt = 0; nt < 4; nt++) {
            const int colS = bn + warp_n * 32 + nt * 8 + t * 2;  // global col in [0,256)
            const float a1c0 = sa[colS],       a1c1 = sa[colS + 1];
            const float a2c0 = sa[256 + colS], a2c1 = sa[256 + colS + 1];
            *(float2*)(g_h + (size_t)row * F_DIM + colS) =
                make_float2(acc[mt][nt][0], acc[mt][nt][1]);
            *(float2*)(g_h + (size_t)(row + 8) * F_DIM + colS) =
                make_float2(acc[mt][nt][2], acc[mt][nt][3]);
            f0 += acc[mt][nt][0] * a1c0 + acc[mt][nt][1] * a1c1;
            g0 += acc[mt][nt][0] * a2c0 + acc[mt][nt][1] * a2c1;
            f1 += acc[mt][nt][2] * a1c0 + acc[mt][nt][3] * a1c1;
            g1 += acc[mt][nt][2] * a2c0 + acc[mt][nt][3] * a2c1;
        }
        #pragma unroll
        for (int o = 1; o < 4; o <<= 1) {
            f0 += __shfl_xor_sync(0xffffffffu, f0, o);
            g0 += __shfl_xor_sync(0xffffffffu, g0, o);
            f1 += __shfl_xor_sync(0xffffffffu, f1, o);
            g1 += __shfl_xor_sync(0xffffffffu, g1, o);
        }
        if (t == 0) {
            atomicAdd(g_f + row, f0);
            atomicAdd(g_g + row, g0);
            atomicAdd(g_f + row + 8, f1);
            atomicAdd(g_g + row + 8, g1);
        }
    }
}

// ---------------- 2) rank-sort + inline scatter (last contributor wins) ----------
__global__ void rank_kernel() {
    __shared__ float sj[1024];
    const int tid = threadIdx.x;
    const int bi = blockIdx.x;          // 32
    const int bj = blockIdx.y;          // 8
    const int jbase = bj * 1024;
    *(float4*)&sj[tid * 4] = *(const float4*)(g_g + jbase + tid * 4);
    __syncthreads();
    const int i = bi * 256 + tid;
    const float vi = g_g[i];
    int cnt = 0;
    #pragma unroll 4
    for (int jj = 0; jj < 1024; jj += 4) {
        float4 v = *(const float4*)&sj[jj];
        int j0 = jbase + jj;
        cnt += (v.x < vi) || (v.x == vi && (j0 + 0) < i);
        cnt += (v.y < vi) || (v.y == vi && (j0 + 1) < i);
        cnt += (v.z < vi) || (v.z == vi && (j0 + 2) < i);
        cnt += (v.w < vi) || (v.w == vi && (j0 + 3) < i);
    }
    atomicAdd(&g_rank[i], cnt);
    __threadfence();
    if (atomicAdd(&g_cnt[i], 1) == 7) {   // 8th (last) contributor scatters
        int r = atomicAdd(&g_rank[i], 0); // coherent read of final rank
        g_gs[r] = vi;
        g_gidx[r] = i;
    }
}

// ---------------- 3) scan A: local prefix/suffix per 8-row chunk + aggregates ----
__global__ void scanA_kernel() {          // grid NCHUNK(1024) x 256
    __shared__ int   sidx[CHUNK];
    __shared__ float sw[CHUNK];
    const int blk = blockIdx.x;
    const int c = threadIdx.x;
    const int base = blk * CHUNK;
    if (c < CHUNK) {
        sidx[c] = g_gidx[base + c];
        sw[c] = expf(g_gs[base + c] - g_gs[N_ROWS - 1]);
    }
    __syncthreads();
    float hv[CHUNK];
    #pragma unroll
    for (int r = 0; r < CHUNK; r++)
        hv[r] = g_h[(size_t)sidx[r] * F_DIM + c];
    float run = 0.f;
    #pragma unroll
    for (int r = 0; r < CHUNK; r++) {
        g_loc[(size_t)(base + r) * 512 + c] = run;       // exclusive prefix of H
        run += hv[r];
    }
    g_aggH[blk * F_DIM + c] = run;
    float runE = 0.f;
    #pragma unroll
    for (int r = CHUNK - 1; r >= 0; r--) {
        runE += sw[r] * hv[r];
        g_loc[(size_t)(base + r) * 512 + 256 + c] = runE; // inclusive suffix of w*H
    }
    g_aggE[blk * F_DIM + c] = runE;
    if (c == 0) {
        float runW = 0.f;
        #pragma unroll
        for (int r = CHUNK - 1; r >= 0; r--) {
            runW += sw[r];
            g_lsufW[base + r] = runW;
        }
        g_aggW[blk] = runW;
    }
}

// ---------------- 4) scan B: cross-chunk offsets ----------------
__global__ void scanB_kernel() {          // grid 32 x 256
    const unsigned FULL = 0xffffffffu;
    const int warp = threadIdx.x >> 5, lane = threadIdx.x & 31;
    const int c = blockIdx.x * 8 + warp;  // 0..255
    float carry = 0.f;
    for (int s = 0; s < NCHUNK; s += 32) {
        float v = g_aggH[(s + lane) * F_DIM + c];
        float x = v;
        #pragma unroll
        for (int o = 1; o < 32; o <<= 1) {
            float t = __shfl_up_sync(FULL, x, o);
            if (lane >= o) x += t;
        }
        g_choff[(size_t)(s + lane) * 512 + c] = carry + x - v;   // exclusive prefix
        carry += __shfl_sync(FULL, x, 31);
    }
    float carryE = 0.f;
    for (int s = NCHUNK - 32; s >= 0; s -= 32) {
        float v = g_aggE[(s + lane) * F_DIM + c];
        float x = v;
        #pragma unroll
        for (int o = 1; o < 32; o <<= 1) {
            float t = __shfl_down_sync(FULL, x, o);
            if (lane + o < 32) x += t;
        }
        g_choff[(size_t)(s + lane) * 512 + 256 + c] = carryE + x - v;  // exclusive suffix
        carryE += __shfl_sync(FULL, x, 0);
    }
    if (lane == 0) {
        g_choff[(size_t)NCHUNK * 512 + c] = carry;       // total H (k == 8192 case)
        g_choff[(size_t)NCHUNK * 512 + 256 + c] = 0.f;
        g_loc[(size_t)N_ROWS * 512 + c] = 0.f;           // loc row 8192 = zeros
        g_loc[(size_t)N_ROWS * 512 + 256 + c] = 0.f;
    }
    if (blockIdx.x == 0 && warp == 0) {
        float cw = 0.f;
        for (int s = NCHUNK - 32; s >= 0; s -= 32) {
            float v = g_aggW[s + lane];
            float x = v;
            #pragma unroll
            for (int o = 1; o < 32; o <<= 1) {
                float t = __shfl_down_sync(FULL, x, o);
                if (lane + o < 32) x += t;
            }
            g_choffW[s + lane] = cw + x - v;
            cw += __shfl_sync(FULL, x, 0);
        }
        if (lane == 0) { g_choffW[NCHUNK] = 0.f; g_lsufW[N_ROWS] = 0.f; }
    }
}

// ---------------- 5) output: binary search + compose + elu ----------------
__global__ void out_kernel(float* __restrict__ out) {
    const int warp = threadIdx.x >> 5, lane = threadIdx.x & 31;
    const int i = blockIdx.x * 8 + warp;
    int k; float alpha, beta, inv;
    if (lane == 0) {
        float fi = g_f[i];
        float gmax = g_gs[N_ROWS - 1];
        float t = fi + gmax;
        float thr = -fi;
        int lo = 0, hi = N_ROWS;
        while (lo < hi) {
            int mid = (lo + hi) >> 1;
            if (g_gs[mid] <= thr) lo = mid + 1; else hi = mid;
        }
        k = lo;
        alpha = expf(fminf(t, 0.f));
        beta  = expf(-fmaxf(t, 0.f));
        float sufWk = g_choffW[k >> 3] + g_lsufW[k];
        inv = 1.f / (alpha * sufWk + beta * (float)k);
    }
    k     = __shfl_sync(0xffffffffu, k, 0);
    alpha = __shfl_sync(0xffffffffu, alpha, 0);
    beta  = __shfl_sync(0xffffffffu, beta, 0);
    inv   = __shfl_sync(0xffffffffu, inv, 0);
    const float* loc = g_loc   + (size_t)k * 512;
    const float* cof = g_choff + (size_t)(k >> 3) * 512;
    float4* po = (float4*)(out + (size_t)i * F_DIM);
    #pragma unroll
    for (int j = 0; j < 2; j++) {
        int idx = lane + 32 * j;
        float4 lh = ((const float4*)loc)[idx];
        float4 le = ((const float4*)(loc + 256))[idx];
        float4 ch = ((const float4*)cof)[idx];
        float4 ce = ((const float4*)(cof + 256))[idx];
        float4 y;
        y.x = (alpha * (ce.x + le.x) + beta * (ch.x + lh.x)) * inv;
        y.y = (alpha * (ce.y + le.y) + beta * (ch.y + lh.y)) * inv;
        y.z = (alpha * (ce.z + le.z) + beta * (ch.z + lh.z)) * inv;
        y.w = (alpha * (ce.w + le.w) + beta * (ch.w + lh.w)) * inv;
        y.x = (y.x > 0.f) ? y.x : expm1f(y.x);
        y.y = (y.y > 0.f) ? y.y : expm1f(y.y);
        y.z = (y.z > 0.f) ? y.z : expm1f(y.z);
        y.w = (y.w > 0.f) ? y.w : expm1f(y.w);
        po[idx] = y;
    }
}

// ---------------- launch ----------------
extern "C" void kernel_launch(void* const* d_in, const int* in_sizes, int n_in,
                              void* d_out, int out_size) {
    const float* x = (const float*)d_in[0];
    const float* W = (const float*)d_in[1];
    const float* a = (const float*)d_in[2];
    float* out = (float*)d_out;

    convert_kernel<<<XBLOCKS + WBLOCKS, 256>>>(x, W);

    cudaFuncSetAttribute(gemm_mma_kernel,
                         cudaFuncAttributeMaxDynamicSharedMemorySize, 2 * BUFSZ + 2048);
    gemm_mma_kernel<<<dim3(F_DIM / 128, N_ROWS / 128), 256, 2 * BUFSZ + 2048>>>(a);

    rank_kernel<<<dim3(N_ROWS / 256, 8), 256>>>();
    scanA_kernel<<<NCHUNK, F_DIM>>>();
    scanB_kernel<<<32, 256>>>();
    out_kernel<<<N_ROWS / 8, 256>>>(out);
}

// round 13
// speedup vs baseline: 1.1651x; 1.1651x over previous
#include <cuda_runtime.h>
#include <cuda_bf16.h>
#include <math.h>
#include <cstdint>

#define N_ROWS 8192
#define K_DIM  512
#define F_DIM  256
#define NCHUNK 512
#define CHUNK  16

// ---------------- scratch (device globals) ----------------
__device__ __nv_bfloat16 g_xh[N_ROWS * K_DIM];
__device__ __nv_bfloat16 g_xl[N_ROWS * K_DIM];
__device__ __nv_bfloat16 g_wth[F_DIM * K_DIM];   // W^T hi  [256][512]
__device__ __nv_bfloat16 g_wtl[F_DIM * K_DIM];   // W^T lo
__device__ float g_h[N_ROWS * F_DIM];
__device__ float g_v1[K_DIM];                    // W @ a1
__device__ float g_v2[K_DIM];                    // W @ a2
__device__ float g_f[N_ROWS];
__device__ float g_g[N_ROWS];
__device__ float g_gs[N_ROWS];
__device__ int   g_gidx[N_ROWS];
__device__ int   g_rank[N_ROWS];
__device__ int   g_cnt[N_ROWS];
// local scans: row k = [locH prefix (256) | locE suffix (256)]
__device__ float g_loc[(size_t)(N_ROWS + 1) * 512];
// chunk offsets: row b = [choffH (256) | choffE (256)]
__device__ float g_choff[(size_t)(NCHUNK + 1) * 512];
__device__ float g_aggH[NCHUNK * F_DIM];
__device__ float g_aggE[NCHUNK * F_DIM];
__device__ float g_aggW[NCHUNK];
__device__ float g_lsufW[N_ROWS + 1];
__device__ float g_choffW[NCHUNK + 1];

// ---------------- helpers ----------------
__device__ __forceinline__ uint32_t smem_u32(const void* p) {
    uint32_t a;
    asm("{ .reg .u64 t; cvta.to.shared.u64 t, %1; cvt.u32.u64 %0, t; }" : "=r"(a) : "l"(p));
    return a;
}
__device__ __forceinline__ void ldsm_x4(uint32_t (&r)[4], uint32_t addr) {
    asm volatile("ldmatrix.sync.aligned.m8n8.x4.shared.b16 {%0,%1,%2,%3}, [%4];"
                 : "=r"(r[0]), "=r"(r[1]), "=r"(r[2]), "=r"(r[3]) : "r"(addr));
}
__device__ __forceinline__ void mma16816(float (&d)[4], const uint32_t (&a)[4],
                                         uint32_t b0, uint32_t b1) {
    asm volatile(
        "mma.sync.aligned.m16n8k16.row.col.f32.bf16.bf16.f32 "
        "{%0,%1,%2,%3}, {%4,%5,%6,%7}, {%8,%9}, {%0,%1,%2,%3};"
        : "+f"(d[0]), "+f"(d[1]), "+f"(d[2]), "+f"(d[3])
        : "r"(a[0]), "r"(a[1]), "r"(a[2]), "r"(a[3]), "r"(b0), "r"(b1));
}
__device__ __forceinline__ void cp16(uint32_t dst, const void* src) {
    asm volatile("cp.async.cg.shared.global [%0], [%1], 16;" :: "r"(dst), "l"(src));
}

// ---------------- s0.0) convert: x -> (xh,xl), W -> (Wth,Wtl) ----------------
#define XBLOCKS (N_ROWS * K_DIM / 4096)   // 1024 blocks, 16 floats per thread
#define WBLOCKS (K_DIM * F_DIM / 256)     // 512
__global__ void convert_kernel(const float* __restrict__ x, const float* __restrict__ W) {
    if (blockIdx.x < XBLOCKS) {
        const int base = blockIdx.x * 4096;
        float4 v[4];
        #pragma unroll
        for (int l = 0; l < 4; l++)
            v[l] = *(const float4*)(x + base + l * 1024 + threadIdx.x * 4);
        #pragma unroll
        for (int l = 0; l < 4; l++) {
            const int idx = base + l * 1024 + threadIdx.x * 4;
            __nv_bfloat16 h0 = __float2bfloat16_rn(v[l].x), h1 = __float2bfloat16_rn(v[l].y);
            __nv_bfloat16 h2 = __float2bfloat16_rn(v[l].z), h3 = __float2bfloat16_rn(v[l].w);
            __nv_bfloat16 l0 = __float2bfloat16_rn(v[l].x - __bfloat162float(h0));
            __nv_bfloat16 l1 = __float2bfloat16_rn(v[l].y - __bfloat162float(h1));
            __nv_bfloat16 l2 = __float2bfloat16_rn(v[l].z - __bfloat162float(h2));
            __nv_bfloat16 l3 = __float2bfloat16_rn(v[l].w - __bfloat162float(h3));
            __nv_bfloat162* ph = (__nv_bfloat162*)(g_xh + idx);
            __nv_bfloat162* pl = (__nv_bfloat162*)(g_xl + idx);
            ph[0] = __nv_bfloat162(h0, h1); ph[1] = __nv_bfloat162(h2, h3);
            pl[0] = __nv_bfloat162(l0, l1); pl[1] = __nv_bfloat162(l2, l3);
        }
    } else {
        const int idx = (blockIdx.x - XBLOCKS) * 256 + threadIdx.x;  // 0..131071
        const int k = idx >> 8;
        const int n = idx & 255;
        float v = W[idx];
        __nv_bfloat16 h = __float2bfloat16_rn(v);
        __nv_bfloat16 l = __float2bfloat16_rn(v - __bfloat162float(h));
        g_wth[(size_t)n * K_DIM + k] = h;
        g_wtl[(size_t)n * K_DIM + k] = l;
    }
}

// ---------------- s1.0) wv: v1 = W@a1, v2 = W@a2 (+ zero rank/cnt) -----------
__global__ void wv_kernel(const float* __restrict__ W, const float* __restrict__ a) {
    __shared__ float sa[512];
    const int tid = threadIdx.x;          // 256
    sa[tid] = a[tid];
    sa[256 + tid] = a[256 + tid];
    {   // zero-inits: 64 blocks x 256 threads = 16384 = 8192 + 8192
        int t = blockIdx.x * 256 + tid;
        if (t < N_ROWS) g_rank[t] = 0; else g_cnt[t - N_ROWS] = 0;
    }
    __syncthreads();
    const int warp = tid >> 5, lane = tid & 31;
    const int r = blockIdx.x * 8 + warp;  // 0..511
    const float* wr = W + (size_t)r * F_DIM + lane * 8;
    float4 w0 = *(const float4*)(wr);
    float4 w1 = *(const float4*)(wr + 4);
    const int c = lane * 8;
    float s1 = w0.x * sa[c]   + w0.y * sa[c+1] + w0.z * sa[c+2] + w0.w * sa[c+3]
             + w1.x * sa[c+4] + w1.y * sa[c+5] + w1.z * sa[c+6] + w1.w * sa[c+7];
    float s2 = w0.x * sa[256+c]   + w0.y * sa[256+c+1] + w0.z * sa[256+c+2] + w0.w * sa[256+c+3]
             + w1.x * sa[256+c+4] + w1.y * sa[256+c+5] + w1.z * sa[256+c+6] + w1.w * sa[256+c+7];
    #pragma unroll
    for (int o = 16; o > 0; o >>= 1) {
        s1 += __shfl_down_sync(0xffffffffu, s1, o);
        s2 += __shfl_down_sync(0xffffffffu, s2, o);
    }
    if (lane == 0) { g_v1[r] = s1; g_v2[r] = s2; }
}

// ---------------- s1.1) fg: f = x@v1, g = x@v2 ----------------
__global__ void fg_kernel(const float* __restrict__ x) {
    __shared__ float sv[1024];            // v1[512] | v2[512]
    const int tid = threadIdx.x;          // 256
    sv[tid] = g_v1[tid];       sv[256 + tid] = g_v1[256 + tid];
    sv[512 + tid] = g_v2[tid]; sv[768 + tid] = g_v2[256 + tid];
    __syncthreads();
    const int warp = tid >> 5, lane = tid & 31;
    const int i = blockIdx.x * 8 + warp;
    const float* xr = x + (size_t)i * K_DIM;
    float sf = 0.f, sg = 0.f;
    #pragma unroll
    for (int j = 0; j < 4; j++) {
        const int c = lane * 4 + j * 128;
        float4 v = *(const float4*)(xr + c);
        sf += v.x * sv[c]   + v.y * sv[c+1]   + v.z * sv[c+2]   + v.w * sv[c+3];
        sg += v.x * sv[512+c] + v.y * sv[512+c+1] + v.z * sv[512+c+2] + v.w * sv[512+c+3];
    }
    #pragma unroll
    for (int o = 16; o > 0; o >>= 1) {
        sf += __shfl_down_sync(0xffffffffu, sf, o);
        sg += __shfl_down_sync(0xffffffffu, sg, o);
    }
    if (lane == 0) { g_f[i] = sf; g_g[i] = sg; }
}

// ---------------- s1.2) rank-sort + inline scatter ----------------
__global__ void rank_kernel() {
    __shared__ float sj[1024];
    const int tid = threadIdx.x;
    const int bi = blockIdx.x;          // 32
    const int bj = blockIdx.y;          // 8
    const int jbase = bj * 1024;
    *(float4*)&sj[tid * 4] = *(const float4*)(g_g + jbase + tid * 4);
    __syncthreads();
    const int i = bi * 256 + tid;
    const float vi = g_g[i];
    int cnt = 0;
    #pragma unroll 4
    for (int jj = 0; jj < 1024; jj += 4) {
        float4 v = *(const float4*)&sj[jj];
        int j0 = jbase + jj;
        cnt += (v.x < vi) || (v.x == vi && (j0 + 0) < i);
        cnt += (v.y < vi) || (v.y == vi && (j0 + 1) < i);
        cnt += (v.z < vi) || (v.z == vi && (j0 + 2) < i);
        cnt += (v.w < vi) || (v.w == vi && (j0 + 3) < i);
    }
    atomicAdd(&g_rank[i], cnt);
    __threadfence();
    if (atomicAdd(&g_cnt[i], 1) == 7) {   // 8th (last) contributor scatters
        int r = atomicAdd(&g_rank[i], 0); // coherent read of final rank
        g_gs[r] = vi;
        g_gidx[r] = i;
    }
}

// ---------------- s0.1) mma.sync GEMM: 128x128 tile, K-chunk 64 --------------
#define GSTRIDE 72
#define TILE_B  18432
#define BUFSZ   73728

__device__ __forceinline__ void load_chunk_async(uint32_t sb, int buf, int k0,
                                                 int bm, int bn, int tid) {
    uint32_t base = sb + buf * BUFSZ;
    #pragma unroll
    for (int l = 0; l < 4; l++) {
        int idx = tid + l * 256;
        int r = idx >> 3, c8 = (idx & 7) * 8;
        uint32_t off = (uint32_t)(r * GSTRIDE + c8) * 2;
        cp16(base + off,              g_xh  + (size_t)(bm + r) * K_DIM + k0 + c8);
        cp16(base + TILE_B + off,     g_xl  + (size_t)(bm + r) * K_DIM + k0 + c8);
        cp16(base + 2 * TILE_B + off, g_wth + (size_t)(bn + r) * K_DIM + k0 + c8);
        cp16(base + 3 * TILE_B + off, g_wtl + (size_t)(bn + r) * K_DIM + k0 + c8);
    }
}

__global__ void __launch_bounds__(256, 1) gemm_mma_kernel() {
    extern __shared__ char smem[];
    const uint32_t sb = smem_u32(smem);
    const int tid = threadIdx.x;
    const int wid = tid >> 5, lane = tid & 31;
    const int warp_m = wid >> 2;
    const int warp_n = wid & 3;
    const int bm = blockIdx.y * 128;
    const int bn = blockIdx.x * 128;

    float acc[4][4][4];
    #pragma unroll
    for (int mt = 0; mt < 4; mt++)
        #pragma unroll
        for (int nt = 0; nt < 4; nt++)
            #pragma unroll
            for (int r = 0; r < 4; r++) acc[mt][nt][r] = 0.f;

    const int a_row = warp_m * 64 + (lane & 15);
    const int a_col = (lane >> 4) * 8;
    const int b_row = warp_n * 32 + ((lane >> 4) & 1) * 8 + (lane & 7);
    const int b_col = ((lane >> 3) & 1) * 8;

    load_chunk_async(sb, 0, 0, bm, bn, tid);
    asm volatile("cp.async.commit_group;" ::: "memory");

    for (int i = 0; i < 8; i++) {
        asm volatile("cp.async.wait_group 0;" ::: "memory");
        __syncthreads();
        if (i < 7) {
            load_chunk_async(sb, (i & 1) ^ 1, (i + 1) * 64, bm, bn, tid);
            asm volatile("cp.async.commit_group;" ::: "memory");
        }
        const uint32_t bufb = sb + (i & 1) * BUFSZ;
        #pragma unroll
        for (int kk = 0; kk < 4; kk++) {
            uint32_t ah[4][4], al[4][4], bh[2][4], bl[2][4];
            #pragma unroll
            for (int mt = 0; mt < 4; mt++) {
                uint32_t off = (uint32_t)((a_row + mt * 16) * GSTRIDE + kk * 16 + a_col) * 2;
                ldsm_x4(ah[mt], bufb + off);
                ldsm_x4(al[mt], bufb + TILE_B + off);
            }
            #pragma unroll
            for (int np = 0; np < 2; np++) {
                uint32_t off = (uint32_t)((b_row + np * 16) * GSTRIDE + kk * 16 + b_col) * 2;
                ldsm_x4(bh[np], bufb + 2 * TILE_B + off);
                ldsm_x4(bl[np], bufb + 3 * TILE_B + off);
            }
            #pragma unroll
            for (int mt = 0; mt < 4; mt++) {
                #pragma unroll
                for (int nt = 0; nt < 4; nt++) {
                    int np = nt >> 1, p = (nt & 1) * 2;
                    mma16816(acc[mt][nt], ah[mt], bh[np][p], bh[np][p + 1]);
                    mma16816(acc[mt][nt], ah[mt], bl[np][p], bl[np][p + 1]);
                    mma16816(acc[mt][nt], al[mt], bh[np][p], bh[np][p + 1]);
                }
            }
        }
        __syncthreads();
    }

    // epilogue: write h only
    const int g = lane >> 2, t = lane & 3;
    #pragma unroll
    for (int mt = 0; mt < 4; mt++) {
        const int row = bm + warp_m * 64 + mt * 16 + g;
        #pragma unroll
        for (int nt = 0; nt < 4; nt++) {
            const int colS = bn + warp_n * 32 + nt * 8 + t * 2;
            *(float2*)(g_h + (size_t)row * F_DIM + colS) =
                make_float2(acc[mt][nt][0], acc[mt][nt][1]);
            *(float2*)(g_h + (size_t)(row + 8) * F_DIM + colS) =
                make_float2(acc[mt][nt][2], acc[mt][nt][3]);
        }
    }
}

// ---------------- s0.2) scan A: local prefix/suffix per 16-row chunk ----------
__global__ void scanA_kernel() {          // grid NCHUNK(512) x 256
    __shared__ int   sidx[CHUNK];
    __shared__ float sw[CHUNK];
    const int blk = blockIdx.x;
    const int c = threadIdx.x;
    const int base = blk * CHUNK;
    if (c < CHUNK) {
        sidx[c] = g_gidx[base + c];
        sw[c] = expf(g_gs[base + c] - g_gs[N_ROWS - 1]);
    }
    __syncthreads();
    float hv[CHUNK];
    #pragma unroll
    for (int r = 0; r < CHUNK; r++)
        hv[r] = g_h[(size_t)sidx[r] * F_DIM + c];
    float run = 0.f;
    #pragma unroll
    for (int r = 0; r < CHUNK; r++) {
        g_loc[(size_t)(base + r) * 512 + c] = run;       // exclusive prefix of H
        run += hv[r];
    }
    g_aggH[blk * F_DIM + c] = run;
    float runE = 0.f;
    #pragma unroll
    for (int r = CHUNK - 1; r >= 0; r--) {
        runE += sw[r] * hv[r];
        g_loc[(size_t)(base + r) * 512 + 256 + c] = runE; // inclusive suffix of w*H
    }
    g_aggE[blk * F_DIM + c] = runE;
    if (c == 0) {
        float runW = 0.f;
        #pragma unroll
        for (int r = CHUNK - 1; r >= 0; r--) {
            runW += sw[r];
            g_lsufW[base + r] = runW;
        }
        g_aggW[blk] = runW;
    }
}

// ---------------- s0.3) scan B: cross-chunk offsets ----------------
__global__ void scanB_kernel() {          // grid 32 x 256
    const unsigned FULL = 0xffffffffu;
    const int warp = threadIdx.x >> 5, lane = threadIdx.x & 31;
    const int c = blockIdx.x * 8 + warp;  // 0..255
    float carry = 0.f;
    for (int s = 0; s < NCHUNK; s += 32) {
        float v = g_aggH[(s + lane) * F_DIM + c];
        float x = v;
        #pragma unroll
        for (int o = 1; o < 32; o <<= 1) {
            float t = __shfl_up_sync(FULL, x, o);
            if (lane >= o) x += t;
        }
        g_choff[(size_t)(s + lane) * 512 + c] = carry + x - v;   // exclusive prefix
        carry += __shfl_sync(FULL, x, 31);
    }
    float carryE = 0.f;
    for (int s = NCHUNK - 32; s >= 0; s -= 32) {
        float v = g_aggE[(s + lane) * F_DIM + c];
        float x = v;
        #pragma unroll
        for (int o = 1; o < 32; o <<= 1) {
            float t = __shfl_down_sync(FULL, x, o);
            if (lane + o < 32) x += t;
        }
        g_choff[(size_t)(s + lane) * 512 + 256 + c] = carryE + x - v;  // exclusive suffix
        carryE += __shfl_sync(FULL, x, 0);
    }
    if (lane == 0) {
        g_choff[(size_t)NCHUNK * 512 + c] = carry;       // total H (k == 8192 case)
        g_choff[(size_t)NCHUNK * 512 + 256 + c] = 0.f;
        g_loc[(size_t)N_ROWS * 512 + c] = 0.f;           // loc row 8192 = zeros
        g_loc[(size_t)N_ROWS * 512 + 256 + c] = 0.f;
    }
    if (blockIdx.x == 0 && warp == 0) {
        float cw = 0.f;
        for (int s = NCHUNK - 32; s >= 0; s -= 32) {
            float v = g_aggW[s + lane];
            float x = v;
            #pragma unroll
            for (int o = 1; o < 32; o <<= 1) {
                float t = __shfl_down_sync(FULL, x, o);
                if (lane + o < 32) x += t;
            }
            g_choffW[s + lane] = cw + x - v;
            cw += __shfl_sync(FULL, x, 0);
        }
        if (lane == 0) { g_choffW[NCHUNK] = 0.f; g_lsufW[N_ROWS] = 0.f; }
    }
}

// ---------------- s0.4) output: binary search + compose + elu ----------------
__global__ void out_kernel(float* __restrict__ out) {
    const int warp = threadIdx.x >> 5, lane = threadIdx.x & 31;
    const int i = blockIdx.x * 8 + warp;
    int k; float alpha, beta, inv;
    if (lane == 0) {
        float fi = g_f[i];
        float gmax = g_gs[N_ROWS - 1];
        float t = fi + gmax;
        float thr = -fi;
        int lo = 0, hi = N_ROWS;
        while (lo < hi) {
            int mid = (lo + hi) >> 1;
            if (g_gs[mid] <= thr) lo = mid + 1; else hi = mid;
        }
        k = lo;
        alpha = expf(fminf(t, 0.f));
        beta  = expf(-fmaxf(t, 0.f));
        float sufWk = g_choffW[k >> 4] + g_lsufW[k];
        inv = 1.f / (alpha * sufWk + beta * (float)k);
    }
    k     = __shfl_sync(0xffffffffu, k, 0);
    alpha = __shfl_sync(0xffffffffu, alpha, 0);
    beta  = __shfl_sync(0xffffffffu, beta, 0);
    inv   = __shfl_sync(0xffffffffu, inv, 0);
    const float* loc = g_loc   + (size_t)k * 512;
    const float* cof = g_choff + (size_t)(k >> 4) * 512;
    float4* po = (float4*)(out + (size_t)i * F_DIM);
    #pragma unroll
    for (int j = 0; j < 2; j++) {
        int idx = lane + 32 * j;
        float4 lh = ((const float4*)loc)[idx];
        float4 le = ((const float4*)(loc + 256))[idx];
        float4 ch = ((const float4*)cof)[idx];
        float4 ce = ((const float4*)(cof + 256))[idx];
        float4 y;
        y.x = (alpha * (ce.x + le.x) + beta * (ch.x + lh.x)) * inv;
        y.y = (alpha * (ce.y + le.y) + beta * (ch.y + lh.y)) * inv;
        y.z = (alpha * (ce.z + le.z) + beta * (ch.z + lh.z)) * inv;
        y.w = (alpha * (ce.w + le.w) + beta * (ch.w + lh.w)) * inv;
        y.x = (y.x > 0.f) ? y.x : expm1f(y.x);
        y.y = (y.y > 0.f) ? y.y : expm1f(y.y);
        y.z = (y.z > 0.f) ? y.z : expm1f(y.z);
        y.w = (y.w > 0.f) ? y.w : expm1f(y.w);
        po[idx] = y;
    }
}

// ---------------- launch: fork sort-chain onto a side stream ----------------
// Stream/events are created ONCE on the first call (the uncaptured correctness
// run) — creating them during graph capture is an unsafe API and poisons the
// capture. The enqueued work sequence is identical on every call.
extern "C" void kernel_launch(void* const* d_in, const int* in_sizes, int n_in,
                              void* d_out, int out_size) {
    const float* x = (const float*)d_in[0];
    const float* W = (const float*)d_in[1];
    const float* a = (const float*)d_in[2];
    float* out = (float*)d_out;

    static cudaStream_t s1 = nullptr;
    static cudaEvent_t eFork = nullptr, eJoin = nullptr;
    static bool tried = false;
    if (!tried) {
        tried = true;
        if (cudaStreamCreateWithFlags(&s1, cudaStreamNonBlocking) != cudaSuccess) s1 = nullptr;
        if (s1) {
            if (cudaEventCreateWithFlags(&eFork, cudaEventDisableTiming) != cudaSuccess ||
                cudaEventCreateWithFlags(&eJoin, cudaEventDisableTiming) != cudaSuccess) {
                s1 = nullptr;
            }
        }
        cudaFuncSetAttribute(gemm_mma_kernel,
                             cudaFuncAttributeMaxDynamicSharedMemorySize, 2 * BUFSZ);
    }

    if (s1) {
        // fork: s1 branches off the head of the main stream
        cudaEventRecord(eFork, 0);
        cudaStreamWaitEvent(s1, eFork, 0);

        // s1: sort chain (independent of the GEMM)
        wv_kernel<<<64, 256, 0, s1>>>(W, a);
        fg_kernel<<<N_ROWS / 8, 256, 0, s1>>>(x);
        rank_kernel<<<dim3(N_ROWS / 256, 8), 256, 0, s1>>>();
        cudaEventRecord(eJoin, s1);

        // s0: convert + GEMM
        convert_kernel<<<XBLOCKS + WBLOCKS, 256>>>(x, W);
        gemm_mma_kernel<<<dim3(F_DIM / 128, N_ROWS / 128), 256, 2 * BUFSZ>>>();

        // join: scans need both h (s0) and sorted order (s1)
        cudaStreamWaitEvent(0, eJoin, 0);
    } else {
        // fallback: fully serial on the default stream
        wv_kernel<<<64, 256>>>(W, a);
        fg_kernel<<<N_ROWS / 8, 256>>>(x);
        rank_kernel<<<dim3(N_ROWS / 256, 8), 256>>>();
        convert_kernel<<<XBLOCKS + WBLOCKS, 256>>>(x, W);
        gemm_mma_kernel<<<dim3(F_DIM / 128, N_ROWS / 128), 256, 2 * BUFSZ>>>();
    }

    scanA_kernel<<<NCHUNK, F_DIM>>>();
    scanB_kernel<<<32, 256>>>();
    out_kernel<<<N_ROWS / 8, 256>>>(out);
}

// round 14
// speedup vs baseline: 1.2807x; 1.0992x over previous
#include <cuda_runtime.h>
#include <cuda_bf16.h>
#include <math.h>
#include <cstdint>

#define N_ROWS 8192
#define K_DIM  512
#define F_DIM  256
#define NCHUNK 512
#define CHUNK  16

// ---------------- scratch (device globals) ----------------
__device__ __nv_bfloat16 g_wth[F_DIM * K_DIM];   // W^T hi  [256][512]
__device__ __nv_bfloat16 g_wtl[F_DIM * K_DIM];   // W^T lo
__device__ float g_h[N_ROWS * F_DIM];
__device__ float g_f[N_ROWS];
__device__ float g_g[N_ROWS];
__device__ float g_gs[N_ROWS];
__device__ int   g_gidx[N_ROWS];
__device__ int   g_rank[N_ROWS];
__device__ int   g_cnt[N_ROWS];
__device__ float g_loc[(size_t)(N_ROWS + 1) * 512];
__device__ float g_choff[(size_t)(NCHUNK + 1) * 512];
__device__ float g_aggH[NCHUNK * F_DIM];
__device__ float g_aggE[NCHUNK * F_DIM];
__device__ float g_aggW[NCHUNK];
__device__ float g_lsufW[N_ROWS + 1];
__device__ float g_choffW[NCHUNK + 1];

// ---------------- helpers ----------------
__device__ __forceinline__ uint32_t smem_u32(const void* p) {
    uint32_t a;
    asm("{ .reg .u64 t; cvta.to.shared.u64 t, %1; cvt.u32.u64 %0, t; }" : "=r"(a) : "l"(p));
    return a;
}
__device__ __forceinline__ void ldsm_x4(uint32_t (&r)[4], uint32_t addr) {
    asm volatile("ldmatrix.sync.aligned.m8n8.x4.shared.b16 {%0,%1,%2,%3}, [%4];"
                 : "=r"(r[0]), "=r"(r[1]), "=r"(r[2]), "=r"(r[3]) : "r"(addr));
}
__device__ __forceinline__ void mma16816(float (&d)[4], const uint32_t (&a)[4],
                                         uint32_t b0, uint32_t b1) {
    asm volatile(
        "mma.sync.aligned.m16n8k16.row.col.f32.bf16.bf16.f32 "
        "{%0,%1,%2,%3}, {%4,%5,%6,%7}, {%8,%9}, {%0,%1,%2,%3};"
        : "+f"(d[0]), "+f"(d[1]), "+f"(d[2]), "+f"(d[3])
        : "r"(a[0]), "r"(a[1]), "r"(a[2]), "r"(a[3]), "r"(b0), "r"(b1));
}
__device__ __forceinline__ void cp16(uint32_t dst, const void* src) {
    asm volatile("cp.async.cg.shared.global [%0], [%1], 16;" :: "r"(dst), "l"(src));
}
__device__ __forceinline__ uint32_t f2bf2(float a, float b) {
    __nv_bfloat162 t(__float2bfloat16_rn(a), __float2bfloat16_rn(b));
    return *reinterpret_cast<uint32_t*>(&t);
}

// ---------------- 0) W convert + transpose + zero-inits (small) ----------------
#define WBLOCKS (K_DIM * F_DIM / 256)     // 512
__global__ void wconvert_kernel(const float* __restrict__ W) {
    const int idx = blockIdx.x * 256 + threadIdx.x;  // 0..131071
    if (idx < N_ROWS) {
        g_rank[idx] = 0; g_cnt[idx] = 0;
        g_f[idx] = 0.f;  g_g[idx] = 0.f;
    }
    const int k = idx >> 8;
    const int n = idx & 255;
    float v = W[idx];
    __nv_bfloat16 h = __float2bfloat16_rn(v);
    __nv_bfloat16 l = __float2bfloat16_rn(v - __bfloat162float(h));
    g_wth[(size_t)n * K_DIM + k] = h;
    g_wtl[(size_t)n * K_DIM + k] = l;
}

// ---------------- 1) GEMM: h = x @ W, x converted in-kernel ----------------
#define GSTRIDE 72
#define TILE_B  18432
#define BUFSZ   73728
#define SM_A1A2 (2 * BUFSZ)

__device__ __forceinline__ void load_x_regs(float4 (&xv)[8], const float* __restrict__ x,
                                            int bm, int k0, int tid) {
    #pragma unroll
    for (int l = 0; l < 8; l++) {
        int idx = tid + l * 256;
        int r = idx >> 4, c4 = idx & 15;
        xv[l] = *(const float4*)(x + (size_t)(bm + r) * K_DIM + k0 + c4 * 4);
    }
}
__device__ __forceinline__ void sts_x(uint32_t sb, int buf, const float4 (&xv)[8], int tid) {
    uint32_t base = sb + buf * BUFSZ;
    #pragma unroll
    for (int l = 0; l < 8; l++) {
        int idx = tid + l * 256;
        int r = idx >> 4, c4 = idx & 15;
        uint32_t off = (uint32_t)(r * GSTRIDE + c4 * 4) * 2;
        float4 v = xv[l];
        float hx = __bfloat162float(__float2bfloat16_rn(v.x));
        float hy = __bfloat162float(__float2bfloat16_rn(v.y));
        float hz = __bfloat162float(__float2bfloat16_rn(v.z));
        float hw = __bfloat162float(__float2bfloat16_rn(v.w));
        uint32_t hi0 = f2bf2(v.x, v.y), hi1 = f2bf2(v.z, v.w);
        uint32_t lo0 = f2bf2(v.x - hx, v.y - hy), lo1 = f2bf2(v.z - hz, v.w - hw);
        asm volatile("st.shared.v2.b32 [%0], {%1, %2};"
                     :: "r"(base + off), "r"(hi0), "r"(hi1));
        asm volatile("st.shared.v2.b32 [%0], {%1, %2};"
                     :: "r"(base + TILE_B + off), "r"(lo0), "r"(lo1));
    }
}
__device__ __forceinline__ void cp_w(uint32_t sb, int buf, int k0, int bn, int tid) {
    uint32_t base = sb + buf * BUFSZ;
    #pragma unroll
    for (int l = 0; l < 4; l++) {
        int idx = tid + l * 256;
        int r = idx >> 3, c8 = (idx & 7) * 8;
        uint32_t off = (uint32_t)(r * GSTRIDE + c8) * 2;
        cp16(base + 2 * TILE_B + off, g_wth + (size_t)(bn + r) * K_DIM + k0 + c8);
        cp16(base + 3 * TILE_B + off, g_wtl + (size_t)(bn + r) * K_DIM + k0 + c8);
    }
}

__global__ void __launch_bounds__(256, 1) gemm_mma_kernel(const float* __restrict__ x,
                                                          const float* __restrict__ a) {
    extern __shared__ char smem[];
    const uint32_t sb = smem_u32(smem);
    float* sa = (float*)(smem + SM_A1A2);
    const int tid = threadIdx.x;
    const int wid = tid >> 5, lane = tid & 31;
    const int warp_m = wid >> 2;
    const int warp_n = wid & 3;
    const int bm = blockIdx.y * 128;
    const int bn = blockIdx.x * 128;

    float acc[4][4][4];
    #pragma unroll
    for (int mt = 0; mt < 4; mt++)
        #pragma unroll
        for (int nt = 0; nt < 4; nt++)
            #pragma unroll
            for (int r = 0; r < 4; r++) acc[mt][nt][r] = 0.f;

    const int a_row = warp_m * 64 + (lane & 15);
    const int a_col = (lane >> 4) * 8;
    const int b_row = warp_n * 32 + ((lane >> 4) & 1) * 8 + (lane & 7);
    const int b_col = ((lane >> 3) & 1) * 8;

    sa[tid] = a[tid];
    sa[256 + tid] = a[256 + tid];

    float4 xv[8];
    load_x_regs(xv, x, bm, 0, tid);
    cp_w(sb, 0, 0, bn, tid);
    asm volatile("cp.async.commit_group;" ::: "memory");

    for (int i = 0; i < 8; i++) {
        asm volatile("cp.async.wait_group 0;" ::: "memory");
        __syncthreads();                  // W[i] visible; prev-iter MMA done
        const int b = i & 1;
        sts_x(sb, b, xv, tid);            // x[i] bf16 hi/lo into smem
        if (i < 7) {
            load_x_regs(xv, x, bm, (i + 1) * 64, tid);   // overlaps MMA below
            cp_w(sb, b ^ 1, (i + 1) * 64, bn, tid);
            asm volatile("cp.async.commit_group;" ::: "memory");
        }
        __syncthreads();                  // xh/xl visible to all warps
        const uint32_t bufb = sb + b * BUFSZ;
        #pragma unroll
        for (int kk = 0; kk < 4; kk++) {
            uint32_t ah[4][4], al[4][4], bh[2][4], bl[2][4];
            #pragma unroll
            for (int mt = 0; mt < 4; mt++) {
                uint32_t off = (uint32_t)((a_row + mt * 16) * GSTRIDE + kk * 16 + a_col) * 2;
                ldsm_x4(ah[mt], bufb + off);
                ldsm_x4(al[mt], bufb + TILE_B + off);
            }
            #pragma unroll
            for (int np = 0; np < 2; np++) {
                uint32_t off = (uint32_t)((b_row + np * 16) * GSTRIDE + kk * 16 + b_col) * 2;
                ldsm_x4(bh[np], bufb + 2 * TILE_B + off);
                ldsm_x4(bl[np], bufb + 3 * TILE_B + off);
            }
            #pragma unroll
            for (int mt = 0; mt < 4; mt++) {
                #pragma unroll
                for (int nt = 0; nt < 4; nt++) {
                    int np = nt >> 1, p = (nt & 1) * 2;
                    mma16816(acc[mt][nt], ah[mt], bh[np][p], bh[np][p + 1]);
                    mma16816(acc[mt][nt], ah[mt], bl[np][p], bl[np][p + 1]);
                    mma16816(acc[mt][nt], al[mt], bh[np][p], bh[np][p + 1]);
                }
            }
        }
        __syncthreads();
    }

    // epilogue: write h + fused f/g partial dot products (R7-proven)
    const int g = lane >> 2, t = lane & 3;
    #pragma unroll
    for (int mt = 0; mt < 4; mt++) {
        const int row = bm + warp_m * 64 + mt * 16 + g;
        float f0 = 0.f, g0 = 0.f, f1 = 0.f, g1 = 0.f;
        #pragma unroll
        for (int nt = 0; nt < 4; nt++) {
            const int colS = bn + warp_n * 32 + nt * 8 + t * 2;
            const float a1c0 = sa[colS],       a1c1 = sa[colS + 1];
            const float a2c0 = sa[256 + colS], a2c1 = sa[256 + colS + 1];
            *(float2*)(g_h + (size_t)row * F_DIM + colS) =
                make_float2(acc[mt][nt][0], acc[mt][nt][1]);
            *(float2*)(g_h + (size_t)(row + 8) * F_DIM + colS) =
                make_float2(acc[mt][nt][2], acc[mt][nt][3]);
            f0 += acc[mt][nt][0] * a1c0 + acc[mt][nt][1] * a1c1;
            g0 += acc[mt][nt][0] * a2c0 + acc[mt][nt][1] * a2c1;
            f1 += acc[mt][nt][2] * a1c0 + acc[mt][nt][3] * a1c1;
            g1 += acc[mt][nt][2] * a2c0 + acc[mt][nt][3] * a2c1;
        }
        #pragma unroll
        for (int o = 1; o < 4; o <<= 1) {
            f0 += __shfl_xor_sync(0xffffffffu, f0, o);
            g0 += __shfl_xor_sync(0xffffffffu, g0, o);
            f1 += __shfl_xor_sync(0xffffffffu, f1, o);
            g1 += __shfl_xor_sync(0xffffffffu, g1, o);
        }
        if (t == 0) {
            atomicAdd(g_f + row, f0);
            atomicAdd(g_g + row, g0);
            atomicAdd(g_f + row + 8, f1);
            atomicAdd(g_g + row + 8, g1);
        }
    }
}

// ---------------- 2) rank-sort + inline scatter ----------------
__global__ void rank_kernel() {
    __shared__ float sj[1024];
    const int tid = threadIdx.x;
    const int bi = blockIdx.x;          // 32
    const int bj = blockIdx.y;          // 8
    const int jbase = bj * 1024;
    *(float4*)&sj[tid * 4] = *(const float4*)(g_g + jbase + tid * 4);
    __syncthreads();
    const int i = bi * 256 + tid;
    const float vi = g_g[i];
    int cnt = 0;
    #pragma unroll 4
    for (int jj = 0; jj < 1024; jj += 4) {
        float4 v = *(const float4*)&sj[jj];
        int j0 = jbase + jj;
        cnt += (v.x < vi) || (v.x == vi && (j0 + 0) < i);
        cnt += (v.y < vi) || (v.y == vi && (j0 + 1) < i);
        cnt += (v.z < vi) || (v.z == vi && (j0 + 2) < i);
        cnt += (v.w < vi) || (v.w == vi && (j0 + 3) < i);
    }
    atomicAdd(&g_rank[i], cnt);
    __threadfence();
    if (atomicAdd(&g_cnt[i], 1) == 7) {
        int r = atomicAdd(&g_rank[i], 0);
        g_gs[r] = vi;
        g_gidx[r] = i;
    }
}

// ---------------- 3) scan A ----------------
__global__ void scanA_kernel() {
    __shared__ int   sidx[CHUNK];
    __shared__ float sw[CHUNK];
    const int blk = blockIdx.x;
    const int c = threadIdx.x;
    const int base = blk * CHUNK;
    if (c < CHUNK) {
        sidx[c] = g_gidx[base + c];
        sw[c] = expf(g_gs[base + c] - g_gs[N_ROWS - 1]);
    }
    __syncthreads();
    float hv[CHUNK];
    #pragma unroll
    for (int r = 0; r < CHUNK; r++)
        hv[r] = g_h[(size_t)sidx[r] * F_DIM + c];
    float run = 0.f;
    #pragma unroll
    for (int r = 0; r < CHUNK; r++) {
        g_loc[(size_t)(base + r) * 512 + c] = run;
        run += hv[r];
    }
    g_aggH[blk * F_DIM + c] = run;
    float runE = 0.f;
    #pragma unroll
    for (int r = CHUNK - 1; r >= 0; r--) {
        runE += sw[r] * hv[r];
        g_loc[(size_t)(base + r) * 512 + 256 + c] = runE;
    }
    g_aggE[blk * F_DIM + c] = runE;
    if (c == 0) {
        float runW = 0.f;
        #pragma unroll
        for (int r = CHUNK - 1; r >= 0; r--) {
            runW += sw[r];
            g_lsufW[base + r] = runW;
        }
        g_aggW[blk] = runW;
    }
}

// ---------------- 4) scan B ----------------
__global__ void scanB_kernel() {
    const unsigned FULL = 0xffffffffu;
    const int warp = threadIdx.x >> 5, lane = threadIdx.x & 31;
    const int c = blockIdx.x * 8 + warp;
    float carry = 0.f;
    for (int s = 0; s < NCHUNK; s += 32) {
        float v = g_aggH[(s + lane) * F_DIM + c];
        float x = v;
        #pragma unroll
        for (int o = 1; o < 32; o <<= 1) {
            float t = __shfl_up_sync(FULL, x, o);
            if (lane >= o) x += t;
        }
        g_choff[(size_t)(s + lane) * 512 + c] = carry + x - v;
        carry += __shfl_sync(FULL, x, 31);
    }
    float carryE = 0.f;
    for (int s = NCHUNK - 32; s >= 0; s -= 32) {
        float v = g_aggE[(s + lane) * F_DIM + c];
        float x = v;
        #pragma unroll
        for (int o = 1; o < 32; o <<= 1) {
            float t = __shfl_down_sync(FULL, x, o);
            if (lane + o < 32) x += t;
        }
        g_choff[(size_t)(s + lane) * 512 + 256 + c] = carryE + x - v;
        carryE += __shfl_sync(FULL, x, 0);
    }
    if (lane == 0) {
        g_choff[(size_t)NCHUNK * 512 + c] = carry;
        g_choff[(size_t)NCHUNK * 512 + 256 + c] = 0.f;
        g_loc[(size_t)N_ROWS * 512 + c] = 0.f;
        g_loc[(size_t)N_ROWS * 512 + 256 + c] = 0.f;
    }
    if (blockIdx.x == 0 && warp == 0) {
        float cw = 0.f;
        for (int s = NCHUNK - 32; s >= 0; s -= 32) {
            float v = g_aggW[s + lane];
            float x = v;
            #pragma unroll
            for (int o = 1; o < 32; o <<= 1) {
                float t = __shfl_down_sync(FULL, x, o);
                if (lane + o < 32) x += t;
            }
            g_choffW[s + lane] = cw + x - v;
            cw += __shfl_sync(FULL, x, 0);
        }
        if (lane == 0) { g_choffW[NCHUNK] = 0.f; g_lsufW[N_ROWS] = 0.f; }
    }
}

// ---------------- 5) output ----------------
__global__ void out_kernel(float* __restrict__ out) {
    const int warp = threadIdx.x >> 5, lane = threadIdx.x & 31;
    const int i = blockIdx.x * 8 + warp;
    int k; float alpha, beta, inv;
    if (lane == 0) {
        float fi = g_f[i];
        float gmax = g_gs[N_ROWS - 1];
        float t = fi + gmax;
        float thr = -fi;
        int lo = 0, hi = N_ROWS;
        while (lo < hi) {
            int mid = (lo + hi) >> 1;
            if (g_gs[mid] <= thr) lo = mid + 1; else hi = mid;
        }
        k = lo;
        alpha = expf(fminf(t, 0.f));
        beta  = expf(-fmaxf(t, 0.f));
        float sufWk = g_choffW[k >> 4] + g_lsufW[k];
        inv = 1.f / (alpha * sufWk + beta * (float)k);
    }
    k     = __shfl_sync(0xffffffffu, k, 0);
    alpha = __shfl_sync(0xffffffffu, alpha, 0);
    beta  = __shfl_sync(0xffffffffu, beta, 0);
    inv   = __shfl_sync(0xffffffffu, inv, 0);
    const float* loc = g_loc   + (size_t)k * 512;
    const float* cof = g_choff + (size_t)(k >> 4) * 512;
    float4* po = (float4*)(out + (size_t)i * F_DIM);
    #pragma unroll
    for (int j = 0; j < 2; j++) {
        int idx = lane + 32 * j;
        float4 lh = ((const float4*)loc)[idx];
        float4 le = ((const float4*)(loc + 256))[idx];
        float4 ch = ((const float4*)cof)[idx];
        float4 ce = ((const float4*)(cof + 256))[idx];
        float4 y;
        y.x = (alpha * (ce.x + le.x) + beta * (ch.x + lh.x)) * inv;
        y.y = (alpha * (ce.y + le.y) + beta * (ch.y + lh.y)) * inv;
        y.z = (alpha * (ce.z + le.z) + beta * (ch.z + lh.z)) * inv;
        y.w = (alpha * (ce.w + le.w) + beta * (ch.w + lh.w)) * inv;
        y.x = (y.x > 0.f) ? y.x : expm1f(y.x);
        y.y = (y.y > 0.f) ? y.y : expm1f(y.y);
        y.z = (y.z > 0.f) ? y.z : expm1f(y.z);
        y.w = (y.w > 0.f) ? y.w : expm1f(y.w);
        po[idx] = y;
    }
}

// ---------------- launch ----------------
extern "C" void kernel_launch(void* const* d_in, const int* in_sizes, int n_in,
                              void* d_out, int out_size) {
    const float* x = (const float*)d_in[0];
    const float* W = (const float*)d_in[1];
    const float* a = (const float*)d_in[2];
    float* out = (float*)d_out;

    wconvert_kernel<<<WBLOCKS, 256>>>(W);

    cudaFuncSetAttribute(gemm_mma_kernel,
                         cudaFuncAttributeMaxDynamicSharedMemorySize, 2 * BUFSZ + 2048);
    gemm_mma_kernel<<<dim3(F_DIM / 128, N_ROWS / 128), 256, 2 * BUFSZ + 2048>>>(x, a);

    rank_kernel<<<dim3(N_ROWS / 256, 8), 256>>>();
    scanA_kernel<<<NCHUNK, F_DIM>>>();
    scanB_kernel<<<32, 256>>>();
    out_kernel<<<N_ROWS / 8, 256>>>(out);
}

// round 15
// speedup vs baseline: 1.4564x; 1.1372x over previous
#include <cuda_runtime.h>
#include <cuda_fp16.h>
#include <math.h>
#include <cstdint>

#define N_ROWS 8192
#define K_DIM  512
#define F_DIM  256
#define NCHUNK 512
#define CHUNK  16

// ---------------- scratch (device globals) ----------------
__device__ __half g_wt[F_DIM * K_DIM];           // W^T fp16  [256][512]
__device__ float g_h[N_ROWS * F_DIM];
__device__ float g_f[N_ROWS];
__device__ float g_g[N_ROWS];
__device__ float g_gs[N_ROWS];
__device__ int   g_gidx[N_ROWS];
__device__ int   g_rank[N_ROWS];
__device__ int   g_cnt[N_ROWS];
__device__ float g_loc[(size_t)(N_ROWS + 1) * 512];
__device__ float g_choff[(size_t)(NCHUNK + 1) * 512];
__device__ float g_aggH[NCHUNK * F_DIM];
__device__ float g_aggE[NCHUNK * F_DIM];
__device__ float g_aggW[NCHUNK];
__device__ float g_lsufW[N_ROWS + 1];
__device__ float g_choffW[NCHUNK + 1];

// ---------------- helpers ----------------
__device__ __forceinline__ uint32_t smem_u32(const void* p) {
    uint32_t a;
    asm("{ .reg .u64 t; cvta.to.shared.u64 t, %1; cvt.u32.u64 %0, t; }" : "=r"(a) : "l"(p));
    return a;
}
__device__ __forceinline__ void ldsm_x4(uint32_t (&r)[4], uint32_t addr) {
    asm volatile("ldmatrix.sync.aligned.m8n8.x4.shared.b16 {%0,%1,%2,%3}, [%4];"
                 : "=r"(r[0]), "=r"(r[1]), "=r"(r[2]), "=r"(r[3]) : "r"(addr));
}
__device__ __forceinline__ void mma16816(float (&d)[4], const uint32_t (&a)[4],
                                         uint32_t b0, uint32_t b1) {
    asm volatile(
        "mma.sync.aligned.m16n8k16.row.col.f32.f16.f16.f32 "
        "{%0,%1,%2,%3}, {%4,%5,%6,%7}, {%8,%9}, {%0,%1,%2,%3};"
        : "+f"(d[0]), "+f"(d[1]), "+f"(d[2]), "+f"(d[3])
        : "r"(a[0]), "r"(a[1]), "r"(a[2]), "r"(a[3]), "r"(b0), "r"(b1));
}
__device__ __forceinline__ void cp16(uint32_t dst, const void* src) {
    asm volatile("cp.async.cg.shared.global [%0], [%1], 16;" :: "r"(dst), "l"(src));
}
__device__ __forceinline__ uint32_t f2h2(float a, float b) {
    __half2 t(__float2half_rn(a), __float2half_rn(b));
    return *reinterpret_cast<uint32_t*>(&t);
}

// ---------------- 0) W convert + transpose + zero-inits (small) ----------------
#define WBLOCKS (K_DIM * F_DIM / 256)     // 512
__global__ void wconvert_kernel(const float* __restrict__ W) {
    const int idx = blockIdx.x * 256 + threadIdx.x;  // 0..131071
    if (idx < N_ROWS) {
        g_rank[idx] = 0; g_cnt[idx] = 0;
        g_f[idx] = 0.f;  g_g[idx] = 0.f;
    }
    const int k = idx >> 8;
    const int n = idx & 255;
    g_wt[(size_t)n * K_DIM + k] = __float2half_rn(W[idx]);
}

// ---------------- 1) GEMM: h = x @ W, fp16 2-term (x split hi/lo) ----------------
// CTA tile 128x128, K-chunk 64, 256 threads (8 warps 2x4).
// SMEM/buffer: AH(128x72 fp16) AL BH = 3*18432 = 55296.
#define GSTRIDE 72
#define TILE_B  18432
#define BUFSZ   55296
#define SM_A1A2 (2 * BUFSZ)

__device__ __forceinline__ void load_x_regs(float4 (&xv)[8], const float* __restrict__ x,
                                            int bm, int k0, int tid) {
    #pragma unroll
    for (int l = 0; l < 8; l++) {
        int idx = tid + l * 256;
        int r = idx >> 4, c4 = idx & 15;
        xv[l] = *(const float4*)(x + (size_t)(bm + r) * K_DIM + k0 + c4 * 4);
    }
}
__device__ __forceinline__ void sts_x(uint32_t sb, int buf, const float4 (&xv)[8], int tid) {
    uint32_t base = sb + buf * BUFSZ;
    #pragma unroll
    for (int l = 0; l < 8; l++) {
        int idx = tid + l * 256;
        int r = idx >> 4, c4 = idx & 15;
        uint32_t off = (uint32_t)(r * GSTRIDE + c4 * 4) * 2;
        float4 v = xv[l];
        float hx = __half2float(__float2half_rn(v.x));
        float hy = __half2float(__float2half_rn(v.y));
        float hz = __half2float(__float2half_rn(v.z));
        float hw = __half2float(__float2half_rn(v.w));
        uint32_t hi0 = f2h2(v.x, v.y), hi1 = f2h2(v.z, v.w);
        uint32_t lo0 = f2h2(v.x - hx, v.y - hy), lo1 = f2h2(v.z - hz, v.w - hw);
        asm volatile("st.shared.v2.b32 [%0], {%1, %2};"
                     :: "r"(base + off), "r"(hi0), "r"(hi1));
        asm volatile("st.shared.v2.b32 [%0], {%1, %2};"
                     :: "r"(base + TILE_B + off), "r"(lo0), "r"(lo1));
    }
}
__device__ __forceinline__ void cp_w(uint32_t sb, int buf, int k0, int bn, int tid) {
    uint32_t base = sb + buf * BUFSZ;
    #pragma unroll
    for (int l = 0; l < 4; l++) {
        int idx = tid + l * 256;
        int r = idx >> 3, c8 = (idx & 7) * 8;
        uint32_t off = (uint32_t)(r * GSTRIDE + c8) * 2;
        cp16(base + 2 * TILE_B + off, g_wt + (size_t)(bn + r) * K_DIM + k0 + c8);
    }
}

__global__ void __launch_bounds__(256, 1) gemm_mma_kernel(const float* __restrict__ x,
                                                          const float* __restrict__ a) {
    extern __shared__ char smem[];
    const uint32_t sb = smem_u32(smem);
    float* sa = (float*)(smem + SM_A1A2);
    const int tid = threadIdx.x;
    const int wid = tid >> 5, lane = tid & 31;
    const int warp_m = wid >> 2;
    const int warp_n = wid & 3;
    const int bm = blockIdx.y * 128;
    const int bn = blockIdx.x * 128;

    float acc[4][4][4];
    #pragma unroll
    for (int mt = 0; mt < 4; mt++)
        #pragma unroll
        for (int nt = 0; nt < 4; nt++)
            #pragma unroll
            for (int r = 0; r < 4; r++) acc[mt][nt][r] = 0.f;

    const int a_row = warp_m * 64 + (lane & 15);
    const int a_col = (lane >> 4) * 8;
    const int b_row = warp_n * 32 + ((lane >> 4) & 1) * 8 + (lane & 7);
    const int b_col = ((lane >> 3) & 1) * 8;

    sa[tid] = a[tid];
    sa[256 + tid] = a[256 + tid];

    float4 xv[8];
    load_x_regs(xv, x, bm, 0, tid);
    cp_w(sb, 0, 0, bn, tid);
    asm volatile("cp.async.commit_group;" ::: "memory");

    for (int i = 0; i < 8; i++) {
        asm volatile("cp.async.wait_group 0;" ::: "memory");
        __syncthreads();                  // W[i] visible; prev-iter MMA done
        const int b = i & 1;
        sts_x(sb, b, xv, tid);            // x[i] fp16 hi/lo into smem
        if (i < 7) {
            load_x_regs(xv, x, bm, (i + 1) * 64, tid);   // overlaps MMA below
            cp_w(sb, b ^ 1, (i + 1) * 64, bn, tid);
            asm volatile("cp.async.commit_group;" ::: "memory");
        }
        __syncthreads();                  // xh/xl visible to all warps
        const uint32_t bufb = sb + b * BUFSZ;
        #pragma unroll
        for (int kk = 0; kk < 4; kk++) {
            uint32_t ah[4][4], al[4][4], bh[2][4];
            #pragma unroll
            for (int mt = 0; mt < 4; mt++) {
                uint32_t off = (uint32_t)((a_row + mt * 16) * GSTRIDE + kk * 16 + a_col) * 2;
                ldsm_x4(ah[mt], bufb + off);
                ldsm_x4(al[mt], bufb + TILE_B + off);
            }
            #pragma unroll
            for (int np = 0; np < 2; np++) {
                uint32_t off = (uint32_t)((b_row + np * 16) * GSTRIDE + kk * 16 + b_col) * 2;
                ldsm_x4(bh[np], bufb + 2 * TILE_B + off);
            }
            #pragma unroll
            for (int mt = 0; mt < 4; mt++) {
                #pragma unroll
                for (int nt = 0; nt < 4; nt++) {
                    int np = nt >> 1, p = (nt & 1) * 2;
                    mma16816(acc[mt][nt], ah[mt], bh[np][p], bh[np][p + 1]);
                    mma16816(acc[mt][nt], al[mt], bh[np][p], bh[np][p + 1]);
                }
            }
        }
        __syncthreads();
    }

    // epilogue: write h + fused f/g partial dot products
    const int g = lane >> 2, t = lane & 3;
    #pragma unroll
    for (int mt = 0; mt < 4; mt++) {
        const int row = bm + warp_m * 64 + mt * 16 + g;
        float f0 = 0.f, g0 = 0.f, f1 = 0.f, g1 = 0.f;
        #pragma unroll
        for (int nt = 0; nt < 4; nt++) {
            const int colS = bn + warp_n * 32 + nt * 8 + t * 2;
            const float a1c0 = sa[colS],       a1c1 = sa[colS + 1];
            const float a2c0 = sa[256 + colS], a2c1 = sa[256 + colS + 1];
            *(float2*)(g_h + (size_t)row * F_DIM + colS) =
                make_float2(acc[mt][nt][0], acc[mt][nt][1]);
            *(float2*)(g_h + (size_t)(row + 8) * F_DIM + colS) =
                make_float2(acc[mt][nt][2], acc[mt][nt][3]);
            f0 += acc[mt][nt][0] * a1c0 + acc[mt][nt][1] * a1c1;
            g0 += acc[mt][nt][0] * a2c0 + acc[mt][nt][1] * a2c1;
            f1 += acc[mt][nt][2] * a1c0 + acc[mt][nt][3] * a1c1;
            g1 += acc[mt][nt][2] * a2c0 + acc[mt][nt][3] * a2c1;
        }
        #pragma unroll
        for (int o = 1; o < 4; o <<= 1) {
            f0 += __shfl_xor_sync(0xffffffffu, f0, o);
            g0 += __shfl_xor_sync(0xffffffffu, g0, o);
            f1 += __shfl_xor_sync(0xffffffffu, f1, o);
            g1 += __shfl_xor_sync(0xffffffffu, g1, o);
        }
        if (t == 0) {
            atomicAdd(g_f + row, f0);
            atomicAdd(g_g + row, g0);
            atomicAdd(g_f + row + 8, f1);
            atomicAdd(g_g + row + 8, g1);
        }
    }
}

// ---------------- 2) rank-sort + inline scatter ----------------
__global__ void rank_kernel() {
    __shared__ float sj[1024];
    const int tid = threadIdx.x;
    const int bi = blockIdx.x;          // 32
    const int bj = blockIdx.y;          // 8
    const int jbase = bj * 1024;
    *(float4*)&sj[tid * 4] = *(const float4*)(g_g + jbase + tid * 4);
    __syncthreads();
    const int i = bi * 256 + tid;
    const float vi = g_g[i];
    int cnt = 0;
    #pragma unroll 4
    for (int jj = 0; jj < 1024; jj += 4) {
        float4 v = *(const float4*)&sj[jj];
        int j0 = jbase + jj;
        cnt += (v.x < vi) || (v.x == vi && (j0 + 0) < i);
        cnt += (v.y < vi) || (v.y == vi && (j0 + 1) < i);
        cnt += (v.z < vi) || (v.z == vi && (j0 + 2) < i);
        cnt += (v.w < vi) || (v.w == vi && (j0 + 3) < i);
    }
    atomicAdd(&g_rank[i], cnt);
    __threadfence();
    if (atomicAdd(&g_cnt[i], 1) == 7) {
        int r = atomicAdd(&g_rank[i], 0);
        g_gs[r] = vi;
        g_gidx[r] = i;
    }
}

// ---------------- 3) scan A ----------------
__global__ void scanA_kernel() {
    __shared__ int   sidx[CHUNK];
    __shared__ float sw[CHUNK];
    const int blk = blockIdx.x;
    const int c = threadIdx.x;
    const int base = blk * CHUNK;
    if (c < CHUNK) {
        sidx[c] = g_gidx[base + c];
        sw[c] = expf(g_gs[base + c] - g_gs[N_ROWS - 1]);
    }
    __syncthreads();
    float hv[CHUNK];
    #pragma unroll
    for (int r = 0; r < CHUNK; r++)
        hv[r] = g_h[(size_t)sidx[r] * F_DIM + c];
    float run = 0.f;
    #pragma unroll
    for (int r = 0; r < CHUNK; r++) {
        g_loc[(size_t)(base + r) * 512 + c] = run;
        run += hv[r];
    }
    g_aggH[blk * F_DIM + c] = run;
    float runE = 0.f;
    #pragma unroll
    for (int r = CHUNK - 1; r >= 0; r--) {
        runE += sw[r] * hv[r];
        g_loc[(size_t)(base + r) * 512 + 256 + c] = runE;
    }
    g_aggE[blk * F_DIM + c] = runE;
    if (c == 0) {
        float runW = 0.f;
        #pragma unroll
        for (int r = CHUNK - 1; r >= 0; r--) {
            runW += sw[r];
            g_lsufW[base + r] = runW;
        }
        g_aggW[blk] = runW;
    }
}

// ---------------- 4) scan B ----------------
__global__ void scanB_kernel() {
    const unsigned FULL = 0xffffffffu;
    const int warp = threadIdx.x >> 5, lane = threadIdx.x & 31;
    const int c = blockIdx.x * 8 + warp;
    float carry = 0.f;
    for (int s = 0; s < NCHUNK; s += 32) {
        float v = g_aggH[(s + lane) * F_DIM + c];
        float x = v;
        #pragma unroll
        for (int o = 1; o < 32; o <<= 1) {
            float t = __shfl_up_sync(FULL, x, o);
            if (lane >= o) x += t;
        }
        g_choff[(size_t)(s + lane) * 512 + c] = carry + x - v;
        carry += __shfl_sync(FULL, x, 31);
    }
    float carryE = 0.f;
    for (int s = NCHUNK - 32; s >= 0; s -= 32) {
        float v = g_aggE[(s + lane) * F_DIM + c];
        float x = v;
        #pragma unroll
        for (int o = 1; o < 32; o <<= 1) {
            float t = __shfl_down_sync(FULL, x, o);
            if (lane + o < 32) x += t;
        }
        g_choff[(size_t)(s + lane) * 512 + 256 + c] = carryE + x - v;
        carryE += __shfl_sync(FULL, x, 0);
    }
    if (lane == 0) {
        g_choff[(size_t)NCHUNK * 512 + c] = carry;
        g_choff[(size_t)NCHUNK * 512 + 256 + c] = 0.f;
        g_loc[(size_t)N_ROWS * 512 + c] = 0.f;
        g_loc[(size_t)N_ROWS * 512 + 256 + c] = 0.f;
    }
    if (blockIdx.x == 0 && warp == 0) {
        float cw = 0.f;
        for (int s = NCHUNK - 32; s >= 0; s -= 32) {
            float v = g_aggW[s + lane];
            float x = v;
            #pragma unroll
            for (int o = 1; o < 32; o <<= 1) {
                float t = __shfl_down_sync(FULL, x, o);
                if (lane + o < 32) x += t;
            }
            g_choffW[s + lane] = cw + x - v;
            cw += __shfl_sync(FULL, x, 0);
        }
        if (lane == 0) { g_choffW[NCHUNK] = 0.f; g_lsufW[N_ROWS] = 0.f; }
    }
}

// ---------------- 5) output ----------------
__global__ void out_kernel(float* __restrict__ out) {
    const int warp = threadIdx.x >> 5, lane = threadIdx.x & 31;
    const int i = blockIdx.x * 8 + warp;
    int k; float alpha, beta, inv;
    if (lane == 0) {
        float fi = g_f[i];
        float gmax = g_gs[N_ROWS - 1];
        float t = fi + gmax;
        float thr = -fi;
        int lo = 0, hi = N_ROWS;
        while (lo < hi) {
            int mid = (lo + hi) >> 1;
            if (g_gs[mid] <= thr) lo = mid + 1; else hi = mid;
        }
        k = lo;
        alpha = expf(fminf(t, 0.f));
        beta  = expf(-fmaxf(t, 0.f));
        float sufWk = g_choffW[k >> 4] + g_lsufW[k];
        inv = 1.f / (alpha * sufWk + beta * (float)k);
    }
    k     = __shfl_sync(0xffffffffu, k, 0);
    alpha = __shfl_sync(0xffffffffu, alpha, 0);
    beta  = __shfl_sync(0xffffffffu, beta, 0);
    inv   = __shfl_sync(0xffffffffu, inv, 0);
    const float* loc = g_loc   + (size_t)k * 512;
    const float* cof = g_choff + (size_t)(k >> 4) * 512;
    float4* po = (float4*)(out + (size_t)i * F_DIM);
    #pragma unroll
    for (int j = 0; j < 2; j++) {
        int idx = lane + 32 * j;
        float4 lh = ((const float4*)loc)[idx];
        float4 le = ((const float4*)(loc + 256))[idx];
        float4 ch = ((const float4*)cof)[idx];
        float4 ce = ((const float4*)(cof + 256))[idx];
        float4 y;
        y.x = (alpha * (ce.x + le.x) + beta * (ch.x + lh.x)) * inv;
        y.y = (alpha * (ce.y + le.y) + beta * (ch.y + lh.y)) * inv;
        y.z = (alpha * (ce.z + le.z) + beta * (ch.z + lh.z)) * inv;
        y.w = (alpha * (ce.w + le.w) + beta * (ch.w + lh.w)) * inv;
        y.x = (y.x > 0.f) ? y.x : expm1f(y.x);
        y.y = (y.y > 0.f) ? y.y : expm1f(y.y);
        y.z = (y.z > 0.f) ? y.z : expm1f(y.z);
        y.w = (y.w > 0.f) ? y.w : expm1f(y.w);
        po[idx] = y;
    }
}

// ---------------- launch ----------------
extern "C" void kernel_launch(void* const* d_in, const int* in_sizes, int n_in,
                              void* d_out, int out_size) {
    const float* x = (const float*)d_in[0];
    const float* W = (const float*)d_in[1];
    const float* a = (const float*)d_in[2];
    float* out = (float*)d_out;

    wconvert_kernel<<<WBLOCKS, 256>>>(W);

    cudaFuncSetAttribute(gemm_mma_kernel,
                         cudaFuncAttributeMaxDynamicSharedMemorySize, 2 * BUFSZ + 2048);
    gemm_mma_kernel<<<dim3(F_DIM / 128, N_ROWS / 128), 256, 2 * BUFSZ + 2048>>>(x, a);

    rank_kernel<<<dim3(N_ROWS / 256, 8), 256>>>();
    scanA_kernel<<<NCHUNK, F_DIM>>>();
    scanB_kernel<<<32, 256>>>();
    out_kernel<<<N_ROWS / 8, 256>>>(out);
}